// round 13
// baseline (speedup 1.0000x reference)
#include <cuda_runtime.h>
#include <math.h>
#include <stdint.h>

// ---------------------------------------------------------------------------
// Problem constants
// ---------------------------------------------------------------------------
#define NLYR   6
#define BSZ_   4
#define QLEN_  512
#define KLEN_  1024
#define DMOD   1024
#define NHEAD  16
#define DHEAD  64
#define DINNER 4096
#define VOCAB  32000
#define NROWS  (BSZ_ * QLEN_)      /* 2048 */
#define NCROWS (BSZ_ * KLEN_)      /* 4096 */

// ---------------------------------------------------------------------------
// Scratch (static device globals — allocation-free)
// ---------------------------------------------------------------------------
__device__ float g_x    [NROWS  * DMOD];
__device__ float g_xcat [NCROWS * DMOD];
__device__ float g_q    [NROWS  * DMOD];
__device__ float g_kv   [NCROWS * 2 * DMOD];
__device__ float g_rk   [KLEN_  * DMOD];
__device__ float g_pos  [KLEN_  * DMOD];
__device__ float g_vec  [NROWS  * DMOD];
__device__ float g_tmp  [NROWS  * DMOD];
__device__ float g_ffh  [NROWS  * DINNER];
__device__ float g_lgt  [(size_t)NROWS * VOCAB];

// ---------------------------------------------------------------------------
// Small helpers
// ---------------------------------------------------------------------------
__device__ __forceinline__ uint32_t f2tf(float f) {
    uint32_t u;
    asm("cvt.rna.tf32.f32 %0, %1;" : "=r"(u) : "f"(f));
    return u;
}

__device__ __forceinline__ void mma8(float* d, const uint32_t* a, const uint32_t* b) {
    asm volatile(
        "mma.sync.aligned.m16n8k8.row.col.f32.tf32.tf32.f32 "
        "{%0,%1,%2,%3}, {%4,%5,%6,%7}, {%8,%9}, {%0,%1,%2,%3};\n"
        : "+f"(d[0]), "+f"(d[1]), "+f"(d[2]), "+f"(d[3])
        : "r"(a[0]), "r"(a[1]), "r"(a[2]), "r"(a[3]), "r"(b[0]), "r"(b[1]));
}

// ---------------------------------------------------------------------------
// Embedding gather
// ---------------------------------------------------------------------------
__global__ __launch_bounds__(256) void embed_kernel(
    const int* __restrict__ data, const float* __restrict__ emb,
    float* __restrict__ x)
{
    int row = blockIdx.x;
    int tok = data[row];
    const float4* src = (const float4*)(emb + (size_t)tok * DMOD);
    float4*       dst = (float4*)(x + (size_t)row * DMOD);
    dst[threadIdx.x] = src[threadIdx.x];
}

// ---------------------------------------------------------------------------
// Positional embedding
// ---------------------------------------------------------------------------
__global__ __launch_bounds__(512) void posemb_kernel(float* __restrict__ pos)
{
    int p = blockIdx.x;
    int f = threadIdx.x;
    double invf = exp(-((double)(2 * f) / 1024.0) * log(10000.0));
    float ang = (float)((double)(KLEN_ - 1 - p) * invf);
    pos[(size_t)p * DMOD + f]       = sinf(ang);
    pos[(size_t)p * DMOD + 512 + f] = cosf(ang);
}

// ---------------------------------------------------------------------------
// Concat [mem ; x]
// ---------------------------------------------------------------------------
__global__ __launch_bounds__(256) void concat_kernel(
    const float* __restrict__ mem, const float* __restrict__ x,
    float* __restrict__ xc)
{
    int row = blockIdx.x;
    int b = row >> 10, j = row & 1023;
    const float4* src = (j < QLEN_)
        ? (const float4*)(mem + ((size_t)b * QLEN_ + j) * DMOD)
        : (const float4*)(x   + ((size_t)b * QLEN_ + (j - QLEN_)) * DMOD);
    float4* dst = (float4*)(xc + (size_t)row * DMOD);
    dst[threadIdx.x] = src[threadIdx.x];
}

// ---------------------------------------------------------------------------
// TF32 tensor-core GEMM, double-buffered smem pipeline.
//   C[M,N] = A[M,K] @ B     (BT=false: B is [K,N];  BT=true: B is [N,K], C=A@B^T)
// Block tile 128x128x32, 256 threads = 8 warps (2m x 4n), warp tile 64x32,
// mma.m16n8k8, fragments pre-permuted in smem (see R11). Ping-pong buffers:
// per ktile each warp prefetches gmem for kt+1, computes from buf[kt&1],
// then scatters into buf[(kt+1)&1]; one __syncthreads per ktile.
// Requires M%128==0, N%128==0, K%32==0. EPI: 0=none, 1=+bias, 2=relu(+bias)
// ---------------------------------------------------------------------------
#define GEMM_SMEM (2 * 8192 * 4)   /* 64 KB dynamic */

template<int EPI, bool BT>
__global__ __launch_bounds__(256, 1) void sgemm_tf32(
    const float* __restrict__ A, const float* __restrict__ Bm,
    const float* __restrict__ bias, float* __restrict__ C,
    int M, int N, int K)
{
    extern __shared__ __align__(16) uint32_t smemU[];   // [2][As 4096 | Bs 4096]

    const int tid  = threadIdx.x;
    const int lane = tid & 31;
    const int wid  = tid >> 5;
    const int wm   = wid >> 2;          // 0..1
    const int wn   = wid & 3;           // 0..3
    const int bm   = blockIdx.y << 7;
    const int bn   = blockIdx.x << 7;

    // ---- gmem pointers --------------------------------------------------
    const int arow = tid >> 1;
    const int acb  = (tid & 1) << 4;
    const float* Ap = A + (size_t)(bm + arow) * K + acb;

    const float* Bp;
    if (BT) {
        Bp = Bm + (size_t)(bn + (tid >> 1)) * K + ((tid & 1) << 4);
    } else {
        Bp = Bm + (size_t)(tid >> 3) * N + bn + ((tid & 7) << 4);
    }

    float4 ra[4], rb[4];
#pragma unroll
    for (int u = 0; u < 4; u++) {
        ra[u] = ((const float4*)Ap)[u];
        rb[u] = ((const float4*)Bp)[u];
    }

    float acc[4][4][4];
#pragma unroll
    for (int mt = 0; mt < 4; mt++)
#pragma unroll
        for (int nt = 0; nt < 4; nt++)
#pragma unroll
            for (int r = 0; r < 4; r++) acc[mt][nt][r] = 0.f;

    const int nk  = K >> 5;
    const int sxA = lane ^ ((lane >> 3) & 3);

    // ---- scatter of (ra, rb) into fragment layout at (AsP, BsP) ----------
    auto scatter = [&](uint32_t* AsP, uint32_t* BsP) {
        {
            const int g4  = (arow & 7) << 2;
            const int hb  = (arow >> 3) & 1;
            const int mt4 = (arow >> 4) << 2;
#pragma unroll
            for (int u = 0; u < 4; u++) {
                float vs[4] = {ra[u].x, ra[u].y, ra[u].z, ra[u].w};
#pragma unroll
                for (int j = 0; j < 4; j++) {
                    int c    = acb + 4 * u + j;
                    int ks   = c >> 3, t = c & 3, w = (c >> 2) & 1;
                    int slot = g4 + t;
                    int sx   = slot ^ ((slot >> 3) & 3);
                    AsP[(((mt4 + ks) << 5) + sx) * 4 + hb + 2 * w] = f2tf(vs[j]);
                }
            }
        }
        if (BT) {
            const int nr  = tid >> 1;
            const int g4  = (nr & 7) << 2;
            const int nt4 = (nr >> 3) << 2;
            const int kcb = (tid & 1) << 4;
#pragma unroll
            for (int u = 0; u < 4; u++) {
                float vs[4] = {rb[u].x, rb[u].y, rb[u].z, rb[u].w};
#pragma unroll
                for (int j = 0; j < 4; j++) {
                    int k    = kcb + 4 * u + j;
                    int ks   = k >> 3, t = k & 3, h = (k >> 2) & 1;
                    int seg  = nt4 + ks;
                    int v    = ((seg & 7) ^ ((seg >> 3) & 7)) << 1;
                    int slot = (g4 + t) ^ v;
                    BsP[((seg << 5) + slot) * 2 + h] = f2tf(vs[j]);
                }
            }
        } else {
            const int kb = tid >> 3;
            const int t  = kb & 3, h = (kb >> 2) & 1, ks = kb >> 3;
            const int nb = (tid & 7) << 4;
#pragma unroll
            for (int u = 0; u < 4; u++) {
                float vs[4] = {rb[u].x, rb[u].y, rb[u].z, rb[u].w};
#pragma unroll
                for (int j = 0; j < 4; j++) {
                    int n    = nb + 4 * u + j;
                    int seg  = ((n >> 3) << 2) + ks;
                    int v    = ((seg & 7) ^ ((seg >> 3) & 7)) << 1;
                    int slot = (((n & 7) << 2) + t) ^ v;
                    BsP[((seg << 5) + slot) * 2 + h] = f2tf(vs[j]);
                }
            }
        }
    };

    // ---- prologue: fill buffer 0 -----------------------------------------
    scatter(smemU, smemU + 4096);
    __syncthreads();

    for (int kt = 0; kt < nk; kt++) {
        const bool more = (kt + 1 < nk);

        // prefetch next ktile from gmem (latency hidden under MMA below)
        if (more) {
            const float* Ap2 = Ap + (size_t)(kt + 1) * 32;
            const float* Bp2 = BT ? Bp + (size_t)(kt + 1) * 32
                                  : Bp + (size_t)(kt + 1) * 32 * N;
#pragma unroll
            for (int u = 0; u < 4; u++) {
                ra[u] = ((const float4*)Ap2)[u];
                rb[u] = ((const float4*)Bp2)[u];
            }
        }

        // compute from current buffer
        const uint32_t* AsP = smemU + ((kt & 1) << 13);
        const uint32_t* BsP = AsP + 4096;
#pragma unroll
        for (int ks = 0; ks < 4; ks++) {
            uint4 af[4];
            uint2 bf[4];
#pragma unroll
            for (int mt = 0; mt < 4; mt++) {
                int seg = ((wm * 4 + mt) << 2) + ks;
                af[mt] = ((const uint4*)AsP)[(seg << 5) + sxA];
            }
#pragma unroll
            for (int nt = 0; nt < 4; nt++) {
                int seg = ((wn * 4 + nt) << 2) + ks;
                int v   = ((seg & 7) ^ ((seg >> 3) & 7)) << 1;
                bf[nt] = ((const uint2*)BsP)[(seg << 5) + (lane ^ v)];
            }
#pragma unroll
            for (int mt = 0; mt < 4; mt++)
#pragma unroll
                for (int nt = 0; nt < 4; nt++)
                    mma8(acc[mt][nt], (const uint32_t*)&af[mt],
                         (const uint32_t*)&bf[nt]);
        }

        // scatter prefetched tile into the other buffer
        if (more) {
            uint32_t* AsN = smemU + (((kt + 1) & 1) << 13);
            scatter(AsN, AsN + 4096);
            __syncthreads();
        }
    }

    // ---- epilogue ---------------------------------------------------------
    const int g  = lane >> 2;
    const int t2 = (lane & 3) << 1;
#pragma unroll
    for (int mt = 0; mt < 4; mt++) {
        int row = bm + wm * 64 + mt * 16 + g;
#pragma unroll
        for (int nt = 0; nt < 4; nt++) {
            int col = bn + wn * 32 + nt * 8 + t2;
            float4 r = {acc[mt][nt][0], acc[mt][nt][1],
                        acc[mt][nt][2], acc[mt][nt][3]};
            if (EPI >= 1) {
                float b0 = bias[col], b1 = bias[col + 1];
                r.x += b0; r.y += b1; r.z += b0; r.w += b1;
            }
            if (EPI == 2) {
                r.x = fmaxf(r.x, 0.f); r.y = fmaxf(r.y, 0.f);
                r.z = fmaxf(r.z, 0.f); r.w = fmaxf(r.w, 0.f);
            }
            *(float2*)&C[(size_t)row * N + col]       = make_float2(r.x, r.y);
            *(float2*)&C[(size_t)(row + 8) * N + col] = make_float2(r.z, r.w);
        }
    }
}

// ---------------------------------------------------------------------------
// Fused relative attention (fp32)
// ---------------------------------------------------------------------------
#define ATTN_SP   17
#define ATTN_SMEM ((KLEN_*ATTN_SP + 1024 + 1024 + 4096 + 16) * 4)

__global__ __launch_bounds__(256) void attn_kernel(
    const float* __restrict__ q,  const float* __restrict__ kv,
    const float* __restrict__ rk, const float* __restrict__ bw,
    const float* __restrict__ br, float* __restrict__ vec)
{
    extern __shared__ float sm[];
    float* s    = sm;
    float* qw   = sm + KLEN_ * ATTN_SP;
    float* qr   = qw + 1024;
    float* red  = qr + 1024;
    float* sinv = red + 4096;

    const int itile = blockIdx.x, n = blockIdx.y, b = blockIdx.z;
    const int tid = threadIdx.x;
    const int i0 = itile << 4;
    const int cmax = i0 + 528;

    for (int u = tid; u < 1024; u += 256) {
        int i = u >> 6, d = u & 63;
        float qv = q[((size_t)(b * QLEN_ + i0 + i) << 10) + n * 64 + d];
        qw[u] = qv + bw[n * 64 + d];
        qr[u] = qv + br[n * 64 + d];
    }
    __syncthreads();

    for (int j = tid; j < cmax; j += 256) {
        const float4* kp = (const float4*)(kv + ((size_t)(b * KLEN_ + j) << 11) + n * 64);
        float4 kr[16];
#pragma unroll
        for (int u = 0; u < 16; u++) kr[u] = kp[u];
#pragma unroll
        for (int i = 0; i < 16; i++) {
            const float4* qp = (const float4*)(qw + (i << 6));
            float acc = 0.f;
#pragma unroll
            for (int u = 0; u < 16; u++) {
                float4 a = qp[u];
                acc += a.x * kr[u].x + a.y * kr[u].y + a.z * kr[u].z + a.w * kr[u].w;
            }
            s[j * ATTN_SP + i] = acc;
        }
    }
    __syncthreads();

    for (int jr = tid; jr < KLEN_; jr += 256) {
        const float4* rp = (const float4*)(rk + ((size_t)jr << 10) + n * 64);
        float4 rr[16];
#pragma unroll
        for (int u = 0; u < 16; u++) rr[u] = rp[u];
#pragma unroll
        for (int i = 0; i < 16; i++) {
            int j = jr + (i0 + i) - 511;
            if (j >= 0) {
                const float4* qp = (const float4*)(qr + (i << 6));
                float acc = 0.f;
#pragma unroll
                for (int u = 0; u < 16; u++) {
                    float4 a = qp[u];
                    acc += a.x * rr[u].x + a.y * rr[u].y + a.z * rr[u].z + a.w * rr[u].w;
                }
                s[j * ATTN_SP + i] += acc;
            }
        }
    }
    __syncthreads();

    {
        int wid = tid >> 5, lane = tid & 31;
        for (int i = wid; i < 16; i += 8) {
            int count = i0 + i + 513;
            float m = -1e30f;
            for (int j = lane; j < count; j += 32)
                m = fmaxf(m, s[j * ATTN_SP + i]);
#pragma unroll
            for (int o = 16; o; o >>= 1)
                m = fmaxf(m, __shfl_xor_sync(0xffffffffu, m, o));
            float sum = 0.f;
            for (int j = lane; j < count; j += 32) {
                float p = expf((s[j * ATTN_SP + i] - m) * 0.125f);
                s[j * ATTN_SP + i] = p;
                sum += p;
            }
#pragma unroll
            for (int o = 16; o; o >>= 1)
                sum += __shfl_xor_sync(0xffffffffu, sum, o);
            if (lane == 0) sinv[i] = 1.f / sum;
            for (int j = count + lane; j < cmax; j += 32)
                s[j * ATTN_SP + i] = 0.f;
        }
    }
    __syncthreads();

    {
        int d = tid & 63, grp = tid >> 6;
        float acc[16];
#pragma unroll
        for (int i = 0; i < 16; i++) acc[i] = 0.f;
        for (int j = grp; j < cmax; j += 4) {
            float vv = kv[((size_t)(b * KLEN_ + j) << 11) + 1024 + n * 64 + d];
#pragma unroll
            for (int i = 0; i < 16; i++)
                acc[i] += s[j * ATTN_SP + i] * vv;
        }
#pragma unroll
        for (int i = 0; i < 16; i++) red[((grp << 4) + i) * 64 + d] = acc[i];
        __syncthreads();
        if (grp == 0) {
#pragma unroll
            for (int i = 0; i < 16; i++) {
                float r0 = red[i * 64 + d] + red[(16 + i) * 64 + d]
                         + red[(32 + i) * 64 + d] + red[(48 + i) * 64 + d];
                vec[((size_t)(b * QLEN_ + i0 + i) << 10) + n * 64 + d] = r0 * sinv[i];
            }
        }
    }
}

// ---------------------------------------------------------------------------
// x = LayerNorm(x + y) * g + b
// ---------------------------------------------------------------------------
__global__ __launch_bounds__(256) void add_ln_kernel(
    float* __restrict__ x, const float* __restrict__ y,
    const float* __restrict__ g, const float* __restrict__ bb)
{
    int row = blockIdx.x, tid = threadIdx.x;
    float* xr = x + (size_t)row * DMOD;
    const float* yr = y + (size_t)row * DMOD;
    float v[4];
    float s = 0.f, sq = 0.f;
#pragma unroll
    for (int u = 0; u < 4; u++) {
        int idx = tid + (u << 8);
        v[u] = xr[idx] + yr[idx];
        s += v[u]; sq += v[u] * v[u];
    }
#pragma unroll
    for (int o = 16; o; o >>= 1) {
        s  += __shfl_xor_sync(0xffffffffu, s,  o);
        sq += __shfl_xor_sync(0xffffffffu, sq, o);
    }
    __shared__ float ws[8], wq[8];
    if ((tid & 31) == 0) { ws[tid >> 5] = s; wq[tid >> 5] = sq; }
    __syncthreads();
    s = 0.f; sq = 0.f;
#pragma unroll
    for (int u = 0; u < 8; u++) { s += ws[u]; sq += wq[u]; }
    float mu   = s * (1.f / DMOD);
    float var  = sq * (1.f / DMOD) - mu * mu;
    float rstd = rsqrtf(var + 1e-5f);
#pragma unroll
    for (int u = 0; u < 4; u++) {
        int idx = tid + (u << 8);
        xr[idx] = (v[u] - mu) * rstd * g[idx] + bb[idx];
    }
}

// ---------------------------------------------------------------------------
// NLL
// ---------------------------------------------------------------------------
__global__ __launch_bounds__(256) void nll_kernel(
    const float* __restrict__ logits, const int* __restrict__ target,
    float* __restrict__ out)
{
    int row = blockIdx.x, tid = threadIdx.x;
    const float* lr = logits + (size_t)row * VOCAB;

    float m = -1e30f;
    for (int j = tid; j < VOCAB; j += 256) m = fmaxf(m, lr[j]);
#pragma unroll
    for (int o = 16; o; o >>= 1) m = fmaxf(m, __shfl_xor_sync(0xffffffffu, m, o));
    __shared__ float wm[8];
    if ((tid & 31) == 0) wm[tid >> 5] = m;
    __syncthreads();
#pragma unroll
    for (int u = 0; u < 8; u++) m = fmaxf(m, wm[u]);

    float s = 0.f;
    for (int j = tid; j < VOCAB; j += 256) s += expf(lr[j] - m);
#pragma unroll
    for (int o = 16; o; o >>= 1) s += __shfl_xor_sync(0xffffffffu, s, o);
    __shared__ float wsum[8];
    if ((tid & 31) == 0) wsum[tid >> 5] = s;
    __syncthreads();

    if (tid == 0) {
        float tot = 0.f;
#pragma unroll
        for (int u = 0; u < 8; u++) tot += wsum[u];
        out[row] = -(lr[target[row]] - m - logf(tot));
    }
}

// ---------------------------------------------------------------------------
// Orchestration
// ---------------------------------------------------------------------------
extern "C" void kernel_launch(void* const* d_in, const int* in_sizes, int n_in,
                              void* d_out, int out_size)
{
    const int*   data   = (const int*)  d_in[0];
    const int*   target = (const int*)  d_in[1];
    const float* memory = (const float*)d_in[2];
    const float* emb    = (const float*)d_in[3];
    const float* Wq     = (const float*)d_in[4];
    const float* Wkv    = (const float*)d_in[5];
    const float* Wr     = (const float*)d_in[6];
    const float* Wo     = (const float*)d_in[7];
    const float* W1     = (const float*)d_in[8];
    const float* b1     = (const float*)d_in[9];
    const float* W2     = (const float*)d_in[10];
    const float* b2     = (const float*)d_in[11];
    const float* g1     = (const float*)d_in[12];
    const float* be1    = (const float*)d_in[13];
    const float* g2     = (const float*)d_in[14];
    const float* be2    = (const float*)d_in[15];
    const float* bw     = (const float*)d_in[16];
    const float* brr    = (const float*)d_in[17];
    float* out = (float*)d_out;

    float *x, *xc, *qb, *kvb, *rkb, *pos, *vecb, *tmp, *ffh, *lg;
    cudaGetSymbolAddress((void**)&x,    g_x);
    cudaGetSymbolAddress((void**)&xc,   g_xcat);
    cudaGetSymbolAddress((void**)&qb,   g_q);
    cudaGetSymbolAddress((void**)&kvb,  g_kv);
    cudaGetSymbolAddress((void**)&rkb,  g_rk);
    cudaGetSymbolAddress((void**)&pos,  g_pos);
    cudaGetSymbolAddress((void**)&vecb, g_vec);
    cudaGetSymbolAddress((void**)&tmp,  g_tmp);
    cudaGetSymbolAddress((void**)&ffh,  g_ffh);
    cudaGetSymbolAddress((void**)&lg,   g_lgt);

    cudaFuncSetAttribute(attn_kernel,
                         cudaFuncAttributeMaxDynamicSharedMemorySize, ATTN_SMEM);
    cudaFuncSetAttribute((const void*)sgemm_tf32<0, false>,
                         cudaFuncAttributeMaxDynamicSharedMemorySize, GEMM_SMEM);
    cudaFuncSetAttribute((const void*)sgemm_tf32<1, false>,
                         cudaFuncAttributeMaxDynamicSharedMemorySize, GEMM_SMEM);
    cudaFuncSetAttribute((const void*)sgemm_tf32<2, false>,
                         cudaFuncAttributeMaxDynamicSharedMemorySize, GEMM_SMEM);
    cudaFuncSetAttribute((const void*)sgemm_tf32<0, true>,
                         cudaFuncAttributeMaxDynamicSharedMemorySize, GEMM_SMEM);

    embed_kernel <<<NROWS, 256>>>(data, emb, x);
    posemb_kernel<<<KLEN_, 512>>>(pos);

    for (int l = 0; l < NLYR; l++) {
        const float* memL = memory + (size_t)l * BSZ_ * QLEN_ * DMOD;

        concat_kernel<<<NCROWS, 256>>>(memL, x, xc);

        // q = x @ Wq[l]                          [2048,1024] x [1024,1024]
        sgemm_tf32<0, false><<<dim3(8, 16), 256, GEMM_SMEM>>>(
            x, Wq + (size_t)l * DMOD * DMOD, nullptr, qb, NROWS, DMOD, DMOD);
        // kv = xcat @ Wkv[l]                     [4096,1024] x [1024,2048]
        sgemm_tf32<0, false><<<dim3(16, 32), 256, GEMM_SMEM>>>(
            xc, Wkv + (size_t)l * DMOD * 2 * DMOD, nullptr, kvb, NCROWS, 2 * DMOD, DMOD);
        // rk = pos @ Wr[l]                       [1024,1024] x [1024,1024]
        sgemm_tf32<0, false><<<dim3(8, 8), 256, GEMM_SMEM>>>(
            pos, Wr + (size_t)l * DMOD * DMOD, nullptr, rkb, KLEN_, DMOD, DMOD);

        attn_kernel<<<dim3(32, 16, 4), 256, ATTN_SMEM>>>(qb, kvb, rkb, bw, brr, vecb);

        // attn_out = vec @ Wo[l]
        sgemm_tf32<0, false><<<dim3(8, 16), 256, GEMM_SMEM>>>(
            vecb, Wo + (size_t)l * DMOD * DMOD, nullptr, tmp, NROWS, DMOD, DMOD);
        add_ln_kernel<<<NROWS, 256>>>(x, tmp, g1 + l * DMOD, be1 + l * DMOD);

        // ff = relu(x @ W1 + b1) @ W2 + b2
        sgemm_tf32<2, false><<<dim3(32, 16), 256, GEMM_SMEM>>>(
            x, W1 + (size_t)l * DMOD * DINNER, b1 + (size_t)l * DINNER,
            ffh, NROWS, DINNER, DMOD);
        sgemm_tf32<1, false><<<dim3(8, 16), 256, GEMM_SMEM>>>(
            ffh, W2 + (size_t)l * DINNER * DMOD, b2 + (size_t)l * DMOD,
            tmp, NROWS, DMOD, DINNER);
        add_ln_kernel<<<NROWS, 256>>>(x, tmp, g2 + l * DMOD, be2 + l * DMOD);
    }

    // logits = x @ emb^T   [2048,1024] x [32000,1024]^T
    sgemm_tf32<0, true><<<dim3(VOCAB / 128, 16), 256, GEMM_SMEM>>>(
        x, emb, nullptr, lg, NROWS, VOCAB, DMOD);

    nll_kernel<<<NROWS, 256>>>(lg, target, out);
}

// round 14
// speedup vs baseline: 1.2171x; 1.2171x over previous
#include <cuda_runtime.h>
#include <math.h>
#include <stdint.h>

// ---------------------------------------------------------------------------
// Problem constants
// ---------------------------------------------------------------------------
#define NLYR   6
#define BSZ_   4
#define QLEN_  512
#define KLEN_  1024
#define DMOD   1024
#define NHEAD  16
#define DHEAD  64
#define DINNER 4096
#define VOCAB  32000
#define NROWS  (BSZ_ * QLEN_)      /* 2048 */
#define NCROWS (BSZ_ * KLEN_)      /* 4096 */

// ---------------------------------------------------------------------------
// Scratch (static device globals — allocation-free)
// ---------------------------------------------------------------------------
__device__ float g_x    [NROWS  * DMOD];
__device__ float g_xcat [NCROWS * DMOD];
__device__ float g_q    [NROWS  * DMOD];
__device__ float g_kv   [NCROWS * 2 * DMOD];
__device__ float g_rk   [KLEN_  * DMOD];
__device__ float g_pos  [KLEN_  * DMOD];
__device__ float g_vec  [NROWS  * DMOD];
__device__ float g_tmp  [NROWS  * DMOD];
__device__ float g_ffh  [NROWS  * DINNER];
__device__ float g_lgt  [(size_t)NROWS * VOCAB];

// ---------------------------------------------------------------------------
// Small helpers
// ---------------------------------------------------------------------------
__device__ __forceinline__ uint32_t pack_bf2(float lo, float hi) {
    uint32_t u;
    asm("cvt.rn.bf16x2.f32 %0, %1, %2;" : "=r"(u) : "f"(hi), "f"(lo));
    return u;
}

__device__ __forceinline__ void mma16(float* d, const uint32_t* a, const uint32_t* b) {
    asm volatile(
        "mma.sync.aligned.m16n8k16.row.col.f32.bf16.bf16.f32 "
        "{%0,%1,%2,%3}, {%4,%5,%6,%7}, {%8,%9}, {%0,%1,%2,%3};\n"
        : "+f"(d[0]), "+f"(d[1]), "+f"(d[2]), "+f"(d[3])
        : "r"(a[0]), "r"(a[1]), "r"(a[2]), "r"(a[3]), "r"(b[0]), "r"(b[1]));
}

// ---------------------------------------------------------------------------
// Embedding gather
// ---------------------------------------------------------------------------
__global__ __launch_bounds__(256) void embed_kernel(
    const int* __restrict__ data, const float* __restrict__ emb,
    float* __restrict__ x)
{
    int row = blockIdx.x;
    int tok = data[row];
    const float4* src = (const float4*)(emb + (size_t)tok * DMOD);
    float4*       dst = (float4*)(x + (size_t)row * DMOD);
    dst[threadIdx.x] = src[threadIdx.x];
}

// ---------------------------------------------------------------------------
// Positional embedding
// ---------------------------------------------------------------------------
__global__ __launch_bounds__(512) void posemb_kernel(float* __restrict__ pos)
{
    int p = blockIdx.x;
    int f = threadIdx.x;
    double invf = exp(-((double)(2 * f) / 1024.0) * log(10000.0));
    float ang = (float)((double)(KLEN_ - 1 - p) * invf);
    pos[(size_t)p * DMOD + f]       = sinf(ang);
    pos[(size_t)p * DMOD + 512 + f] = cosf(ang);
}

// ---------------------------------------------------------------------------
// Concat [mem ; x]
// ---------------------------------------------------------------------------
__global__ __launch_bounds__(256) void concat_kernel(
    const float* __restrict__ mem, const float* __restrict__ x,
    float* __restrict__ xc)
{
    int row = blockIdx.x;
    int b = row >> 10, j = row & 1023;
    const float4* src = (j < QLEN_)
        ? (const float4*)(mem + ((size_t)b * QLEN_ + j) * DMOD)
        : (const float4*)(x   + ((size_t)b * QLEN_ + (j - QLEN_)) * DMOD);
    float4* dst = (float4*)(xc + (size_t)row * DMOD);
    dst[threadIdx.x] = src[threadIdx.x];
}

// ---------------------------------------------------------------------------
// BF16 tensor-core GEMM (fp32 in/out, bf16 compute, fp32 accumulate).
//   C[M,N] = A[M,K] @ B     (BT=false: B is [K,N];  BT=true: B is [N,K], C=A@B^T)
// Block tile 128x128x32, 256 threads = 8 warps (2m x 4n), warp tile 64x32,
// mma.m16n8k16. Single-buffer pipeline with register prefetch (R11 structure).
// Fragments are pre-permuted in smem:
//   A: per (16-row tile mtg, k16-step ks) segment, lane^(seg&7) holds uint4
//      {a0,a1,a2,a3}; consumer LDS.128 conflict-free.
//   B: per (8-col tile ntg, k16-step ks) segment, lane^(ntg&15) holds uint2
//      {b0,b1}; consumer LDS.64 conflict-free.
// Requires M%128==0, N%128==0, K%32==0. EPI: 0=none, 1=+bias, 2=relu(+bias)
// ---------------------------------------------------------------------------
template<int EPI, bool BT>
__global__ __launch_bounds__(256, 1) void gemm_bf16(
    const float* __restrict__ A, const float* __restrict__ Bm,
    const float* __restrict__ bias, float* __restrict__ C,
    int M, int N, int K)
{
    __shared__ __align__(16) uint32_t As[2048];   // 8 KB: 16 segs x 32 lanes x uint4
    __shared__ __align__(16) uint32_t Bs[2048];   // 8 KB: 32 segs x 32 lanes x uint2

    const int tid  = threadIdx.x;
    const int lane = tid & 31;
    const int wid  = tid >> 5;
    const int wm   = wid >> 2;          // 0..1
    const int wn   = wid & 3;           // 0..3
    const int bm   = blockIdx.y << 7;
    const int bn   = blockIdx.x << 7;

    // ---- A loader: row = tid>>1 (128 rows), 16 k at (tid&1)*16 -----------
    const int arow = tid >> 1;
    const int acb  = (tid & 1) << 4;
    const float* Ap = A + (size_t)(bm + arow) * K + acb;

    // ---- B loader ---------------------------------------------------------
    const float* Bp;
    if (BT) {
        // B[N,K]: thread handles n-row tid>>1, 16 consecutive k
        Bp = Bm + (size_t)(bn + (tid >> 1)) * K + ((tid & 1) << 4);
    } else {
        // B[K,N]: thread handles k-pair rows (2kp, 2kp+1), 8 cols at (tid&15)*8
        Bp = Bm + (size_t)((tid >> 4) << 1) * N + bn + ((tid & 15) << 3);
    }

    float4 ra[4], rb[4];
#pragma unroll
    for (int u = 0; u < 4; u++) ra[u] = ((const float4*)Ap)[u];
    if (BT) {
#pragma unroll
        for (int u = 0; u < 4; u++) rb[u] = ((const float4*)Bp)[u];
    } else {
        rb[0] = ((const float4*)Bp)[0];
        rb[1] = ((const float4*)Bp)[1];
        rb[2] = ((const float4*)(Bp + N))[0];
        rb[3] = ((const float4*)(Bp + N))[1];
    }

    float acc[4][4][4];
#pragma unroll
    for (int mt = 0; mt < 4; mt++)
#pragma unroll
        for (int nt = 0; nt < 4; nt++)
#pragma unroll
            for (int r = 0; r < 4; r++) acc[mt][nt][r] = 0.f;

    const int nk = K >> 5;

    for (int kt = 0; kt < nk; kt++) {
        // ---- scatter A into bf16 fragment layout -----------------------
        {
            const int mtg = arow >> 4, r16 = arow & 15;
            const int g = r16 & 7, hb = r16 >> 3;
            const int seg = (mtg << 1) + (tid & 1);
            const int v = seg & 7;
            float vv[16] = {ra[0].x, ra[0].y, ra[0].z, ra[0].w,
                            ra[1].x, ra[1].y, ra[1].z, ra[1].w,
                            ra[2].x, ra[2].y, ra[2].z, ra[2].w,
                            ra[3].x, ra[3].y, ra[3].z, ra[3].w};
#pragma unroll
            for (int p = 0; p < 8; p++) {
                int t = p & 3, kh = p >> 2;
                int ls = ((g << 2) + t) ^ v;
                As[(((seg << 5) + ls) << 2) + hb + (kh << 1)] =
                    pack_bf2(vv[2 * p], vv[2 * p + 1]);
            }
        }
        // ---- scatter B ----------------------------------------------------
        if (BT) {
            const int n = tid >> 1;
            const int g = n & 7, ntg = n >> 3;
            const int ks = tid & 1;
            const int segB = (ntg << 1) + ks;
            const int v = ntg & 15;
            float vv[16] = {rb[0].x, rb[0].y, rb[0].z, rb[0].w,
                            rb[1].x, rb[1].y, rb[1].z, rb[1].w,
                            rb[2].x, rb[2].y, rb[2].z, rb[2].w,
                            rb[3].x, rb[3].y, rb[3].z, rb[3].w};
#pragma unroll
            for (int p = 0; p < 8; p++) {
                int t = p & 3, breg = p >> 2;
                int ls = ((g << 2) + t) ^ v;
                Bs[(((segB << 5) + ls) << 1) + breg] =
                    pack_bf2(vv[2 * p], vv[2 * p + 1]);
            }
        } else {
            const int kp = tid >> 4;                  // 0..15 k-pairs
            const int cg = tid & 15;                  // col group (ntg)
            const int ks = kp >> 3, t = kp & 3, breg = (kp >> 2) & 1;
            const int segB = (cg << 1) + ks;
            const int v = cg & 15;
            float r0[8] = {rb[0].x, rb[0].y, rb[0].z, rb[0].w,
                           rb[1].x, rb[1].y, rb[1].z, rb[1].w};
            float r1[8] = {rb[2].x, rb[2].y, rb[2].z, rb[2].w,
                           rb[3].x, rb[3].y, rb[3].z, rb[3].w};
#pragma unroll
            for (int j = 0; j < 8; j++) {
                int ls = ((j << 2) + t) ^ v;
                Bs[(((segB << 5) + ls) << 1) + breg] = pack_bf2(r0[j], r1[j]);
            }
        }
        __syncthreads();

        // ---- prefetch next ktile into registers ---------------------------
        if (kt + 1 < nk) {
            const float* Ap2 = Ap + (size_t)(kt + 1) * 32;
#pragma unroll
            for (int u = 0; u < 4; u++) ra[u] = ((const float4*)Ap2)[u];
            if (BT) {
                const float* Bp2 = Bp + (size_t)(kt + 1) * 32;
#pragma unroll
                for (int u = 0; u < 4; u++) rb[u] = ((const float4*)Bp2)[u];
            } else {
                const float* Bp2 = Bp + (size_t)(kt + 1) * 32 * N;
                rb[0] = ((const float4*)Bp2)[0];
                rb[1] = ((const float4*)Bp2)[1];
                rb[2] = ((const float4*)(Bp2 + N))[0];
                rb[3] = ((const float4*)(Bp2 + N))[1];
            }
        }

        // ---- compute --------------------------------------------------------
#pragma unroll
        for (int ks = 0; ks < 2; ks++) {
            uint4 af[4];
            uint2 bf[4];
#pragma unroll
            for (int mt = 0; mt < 4; mt++) {
                int seg = (((wm << 2) + mt) << 1) + ks;
                af[mt] = ((const uint4*)As)[(seg << 5) + (lane ^ (seg & 7))];
            }
#pragma unroll
            for (int nt = 0; nt < 4; nt++) {
                int ntg = (wn << 2) + nt;
                int segB = (ntg << 1) + ks;
                bf[nt] = ((const uint2*)Bs)[(segB << 5) + (lane ^ (ntg & 15))];
            }
#pragma unroll
            for (int mt = 0; mt < 4; mt++)
#pragma unroll
                for (int nt = 0; nt < 4; nt++)
                    mma16(acc[mt][nt], (const uint32_t*)&af[mt],
                          (const uint32_t*)&bf[nt]);
        }
        __syncthreads();
    }

    // ---- epilogue -----------------------------------------------------------
    const int g  = lane >> 2;
    const int t2 = (lane & 3) << 1;
#pragma unroll
    for (int mt = 0; mt < 4; mt++) {
        int row = bm + wm * 64 + mt * 16 + g;
#pragma unroll
        for (int nt = 0; nt < 4; nt++) {
            int col = bn + wn * 32 + nt * 8 + t2;
            float4 r = {acc[mt][nt][0], acc[mt][nt][1],
                        acc[mt][nt][2], acc[mt][nt][3]};
            if (EPI >= 1) {
                float b0 = bias[col], b1 = bias[col + 1];
                r.x += b0; r.y += b1; r.z += b0; r.w += b1;
            }
            if (EPI == 2) {
                r.x = fmaxf(r.x, 0.f); r.y = fmaxf(r.y, 0.f);
                r.z = fmaxf(r.z, 0.f); r.w = fmaxf(r.w, 0.f);
            }
            *(float2*)&C[(size_t)row * N + col]       = make_float2(r.x, r.y);
            *(float2*)&C[(size_t)(row + 8) * N + col] = make_float2(r.z, r.w);
        }
    }
}

// ---------------------------------------------------------------------------
// Fused relative attention (fp32)
// ---------------------------------------------------------------------------
#define ATTN_SP   17
#define ATTN_SMEM ((KLEN_*ATTN_SP + 1024 + 1024 + 4096 + 16) * 4)

__global__ __launch_bounds__(256) void attn_kernel(
    const float* __restrict__ q,  const float* __restrict__ kv,
    const float* __restrict__ rk, const float* __restrict__ bw,
    const float* __restrict__ br, float* __restrict__ vec)
{
    extern __shared__ float sm[];
    float* s    = sm;
    float* qw   = sm + KLEN_ * ATTN_SP;
    float* qr   = qw + 1024;
    float* red  = qr + 1024;
    float* sinv = red + 4096;

    const int itile = blockIdx.x, n = blockIdx.y, b = blockIdx.z;
    const int tid = threadIdx.x;
    const int i0 = itile << 4;
    const int cmax = i0 + 528;

    for (int u = tid; u < 1024; u += 256) {
        int i = u >> 6, d = u & 63;
        float qv = q[((size_t)(b * QLEN_ + i0 + i) << 10) + n * 64 + d];
        qw[u] = qv + bw[n * 64 + d];
        qr[u] = qv + br[n * 64 + d];
    }
    __syncthreads();

    for (int j = tid; j < cmax; j += 256) {
        const float4* kp = (const float4*)(kv + ((size_t)(b * KLEN_ + j) << 11) + n * 64);
        float4 kr[16];
#pragma unroll
        for (int u = 0; u < 16; u++) kr[u] = kp[u];
#pragma unroll
        for (int i = 0; i < 16; i++) {
            const float4* qp = (const float4*)(qw + (i << 6));
            float acc = 0.f;
#pragma unroll
            for (int u = 0; u < 16; u++) {
                float4 a = qp[u];
                acc += a.x * kr[u].x + a.y * kr[u].y + a.z * kr[u].z + a.w * kr[u].w;
            }
            s[j * ATTN_SP + i] = acc;
        }
    }
    __syncthreads();

    for (int jr = tid; jr < KLEN_; jr += 256) {
        const float4* rp = (const float4*)(rk + ((size_t)jr << 10) + n * 64);
        float4 rr[16];
#pragma unroll
        for (int u = 0; u < 16; u++) rr[u] = rp[u];
#pragma unroll
        for (int i = 0; i < 16; i++) {
            int j = jr + (i0 + i) - 511;
            if (j >= 0) {
                const float4* qp = (const float4*)(qr + (i << 6));
                float acc = 0.f;
#pragma unroll
                for (int u = 0; u < 16; u++) {
                    float4 a = qp[u];
                    acc += a.x * rr[u].x + a.y * rr[u].y + a.z * rr[u].z + a.w * rr[u].w;
                }
                s[j * ATTN_SP + i] += acc;
            }
        }
    }
    __syncthreads();

    {
        int wid = tid >> 5, lane = tid & 31;
        for (int i = wid; i < 16; i += 8) {
            int count = i0 + i + 513;
            float m = -1e30f;
            for (int j = lane; j < count; j += 32)
                m = fmaxf(m, s[j * ATTN_SP + i]);
#pragma unroll
            for (int o = 16; o; o >>= 1)
                m = fmaxf(m, __shfl_xor_sync(0xffffffffu, m, o));
            float sum = 0.f;
            for (int j = lane; j < count; j += 32) {
                float p = expf((s[j * ATTN_SP + i] - m) * 0.125f);
                s[j * ATTN_SP + i] = p;
                sum += p;
            }
#pragma unroll
            for (int o = 16; o; o >>= 1)
                sum += __shfl_xor_sync(0xffffffffu, sum, o);
            if (lane == 0) sinv[i] = 1.f / sum;
            for (int j = count + lane; j < cmax; j += 32)
                s[j * ATTN_SP + i] = 0.f;
        }
    }
    __syncthreads();

    {
        int d = tid & 63, grp = tid >> 6;
        float acc[16];
#pragma unroll
        for (int i = 0; i < 16; i++) acc[i] = 0.f;
        for (int j = grp; j < cmax; j += 4) {
            float vv = kv[((size_t)(b * KLEN_ + j) << 11) + 1024 + n * 64 + d];
#pragma unroll
            for (int i = 0; i < 16; i++)
                acc[i] += s[j * ATTN_SP + i] * vv;
        }
#pragma unroll
        for (int i = 0; i < 16; i++) red[((grp << 4) + i) * 64 + d] = acc[i];
        __syncthreads();
        if (grp == 0) {
#pragma unroll
            for (int i = 0; i < 16; i++) {
                float r0 = red[i * 64 + d] + red[(16 + i) * 64 + d]
                         + red[(32 + i) * 64 + d] + red[(48 + i) * 64 + d];
                vec[((size_t)(b * QLEN_ + i0 + i) << 10) + n * 64 + d] = r0 * sinv[i];
            }
        }
    }
}

// ---------------------------------------------------------------------------
// x = LayerNorm(x + y) * g + b
// ---------------------------------------------------------------------------
__global__ __launch_bounds__(256) void add_ln_kernel(
    float* __restrict__ x, const float* __restrict__ y,
    const float* __restrict__ g, const float* __restrict__ bb)
{
    int row = blockIdx.x, tid = threadIdx.x;
    float* xr = x + (size_t)row * DMOD;
    const float* yr = y + (size_t)row * DMOD;
    float v[4];
    float s = 0.f, sq = 0.f;
#pragma unroll
    for (int u = 0; u < 4; u++) {
        int idx = tid + (u << 8);
        v[u] = xr[idx] + yr[idx];
        s += v[u]; sq += v[u] * v[u];
    }
#pragma unroll
    for (int o = 16; o; o >>= 1) {
        s  += __shfl_xor_sync(0xffffffffu, s,  o);
        sq += __shfl_xor_sync(0xffffffffu, sq, o);
    }
    __shared__ float ws[8], wq[8];
    if ((tid & 31) == 0) { ws[tid >> 5] = s; wq[tid >> 5] = sq; }
    __syncthreads();
    s = 0.f; sq = 0.f;
#pragma unroll
    for (int u = 0; u < 8; u++) { s += ws[u]; sq += wq[u]; }
    float mu   = s * (1.f / DMOD);
    float var  = sq * (1.f / DMOD) - mu * mu;
    float rstd = rsqrtf(var + 1e-5f);
#pragma unroll
    for (int u = 0; u < 4; u++) {
        int idx = tid + (u << 8);
        xr[idx] = (v[u] - mu) * rstd * g[idx] + bb[idx];
    }
}

// ---------------------------------------------------------------------------
// NLL
// ---------------------------------------------------------------------------
__global__ __launch_bounds__(256) void nll_kernel(
    const float* __restrict__ logits, const int* __restrict__ target,
    float* __restrict__ out)
{
    int row = blockIdx.x, tid = threadIdx.x;
    const float* lr = logits + (size_t)row * VOCAB;

    float m = -1e30f;
    for (int j = tid; j < VOCAB; j += 256) m = fmaxf(m, lr[j]);
#pragma unroll
    for (int o = 16; o; o >>= 1) m = fmaxf(m, __shfl_xor_sync(0xffffffffu, m, o));
    __shared__ float wm[8];
    if ((tid & 31) == 0) wm[tid >> 5] = m;
    __syncthreads();
#pragma unroll
    for (int u = 0; u < 8; u++) m = fmaxf(m, wm[u]);

    float s = 0.f;
    for (int j = tid; j < VOCAB; j += 256) s += expf(lr[j] - m);
#pragma unroll
    for (int o = 16; o; o >>= 1) s += __shfl_xor_sync(0xffffffffu, s, o);
    __shared__ float wsum[8];
    if ((tid & 31) == 0) wsum[tid >> 5] = s;
    __syncthreads();

    if (tid == 0) {
        float tot = 0.f;
#pragma unroll
        for (int u = 0; u < 8; u++) tot += wsum[u];
        out[row] = -(lr[target[row]] - m - logf(tot));
    }
}

// ---------------------------------------------------------------------------
// Orchestration
// ---------------------------------------------------------------------------
extern "C" void kernel_launch(void* const* d_in, const int* in_sizes, int n_in,
                              void* d_out, int out_size)
{
    const int*   data   = (const int*)  d_in[0];
    const int*   target = (const int*)  d_in[1];
    const float* memory = (const float*)d_in[2];
    const float* emb    = (const float*)d_in[3];
    const float* Wq     = (const float*)d_in[4];
    const float* Wkv    = (const float*)d_in[5];
    const float* Wr     = (const float*)d_in[6];
    const float* Wo     = (const float*)d_in[7];
    const float* W1     = (const float*)d_in[8];
    const float* b1     = (const float*)d_in[9];
    const float* W2     = (const float*)d_in[10];
    const float* b2     = (const float*)d_in[11];
    const float* g1     = (const float*)d_in[12];
    const float* be1    = (const float*)d_in[13];
    const float* g2     = (const float*)d_in[14];
    const float* be2    = (const float*)d_in[15];
    const float* bw     = (const float*)d_in[16];
    const float* brr    = (const float*)d_in[17];
    float* out = (float*)d_out;

    float *x, *xc, *qb, *kvb, *rkb, *pos, *vecb, *tmp, *ffh, *lg;
    cudaGetSymbolAddress((void**)&x,    g_x);
    cudaGetSymbolAddress((void**)&xc,   g_xcat);
    cudaGetSymbolAddress((void**)&qb,   g_q);
    cudaGetSymbolAddress((void**)&kvb,  g_kv);
    cudaGetSymbolAddress((void**)&rkb,  g_rk);
    cudaGetSymbolAddress((void**)&pos,  g_pos);
    cudaGetSymbolAddress((void**)&vecb, g_vec);
    cudaGetSymbolAddress((void**)&tmp,  g_tmp);
    cudaGetSymbolAddress((void**)&ffh,  g_ffh);
    cudaGetSymbolAddress((void**)&lg,   g_lgt);

    cudaFuncSetAttribute(attn_kernel,
                         cudaFuncAttributeMaxDynamicSharedMemorySize, ATTN_SMEM);

    embed_kernel <<<NROWS, 256>>>(data, emb, x);
    posemb_kernel<<<KLEN_, 512>>>(pos);

    for (int l = 0; l < NLYR; l++) {
        const float* memL = memory + (size_t)l * BSZ_ * QLEN_ * DMOD;

        concat_kernel<<<NCROWS, 256>>>(memL, x, xc);

        // q = x @ Wq[l]                          [2048,1024] x [1024,1024]
        gemm_bf16<0, false><<<dim3(8, 16), 256>>>(
            x, Wq + (size_t)l * DMOD * DMOD, nullptr, qb, NROWS, DMOD, DMOD);
        // kv = xcat @ Wkv[l]                     [4096,1024] x [1024,2048]
        gemm_bf16<0, false><<<dim3(16, 32), 256>>>(
            xc, Wkv + (size_t)l * DMOD * 2 * DMOD, nullptr, kvb, NCROWS, 2 * DMOD, DMOD);
        // rk = pos @ Wr[l]                       [1024,1024] x [1024,1024]
        gemm_bf16<0, false><<<dim3(8, 8), 256>>>(
            pos, Wr + (size_t)l * DMOD * DMOD, nullptr, rkb, KLEN_, DMOD, DMOD);

        attn_kernel<<<dim3(32, 16, 4), 256, ATTN_SMEM>>>(qb, kvb, rkb, bw, brr, vecb);

        // attn_out = vec @ Wo[l]
        gemm_bf16<0, false><<<dim3(8, 16), 256>>>(
            vecb, Wo + (size_t)l * DMOD * DMOD, nullptr, tmp, NROWS, DMOD, DMOD);
        add_ln_kernel<<<NROWS, 256>>>(x, tmp, g1 + l * DMOD, be1 + l * DMOD);

        // ff = relu(x @ W1 + b1) @ W2 + b2
        gemm_bf16<2, false><<<dim3(32, 16), 256>>>(
            x, W1 + (size_t)l * DMOD * DINNER, b1 + (size_t)l * DINNER,
            ffh, NROWS, DINNER, DMOD);
        gemm_bf16<1, false><<<dim3(8, 16), 256>>>(
            ffh, W2 + (size_t)l * DINNER * DMOD, b2 + (size_t)l * DMOD,
            tmp, NROWS, DMOD, DINNER);
        add_ln_kernel<<<NROWS, 256>>>(x, tmp, g2 + l * DMOD, be2 + l * DMOD);
    }

    // logits = x @ emb^T   [2048,1024] x [32000,1024]^T
    gemm_bf16<0, true><<<dim3(VOCAB / 128, 16), 256>>>(
        x, emb, nullptr, lg, NROWS, VOCAB, DMOD);

    nll_kernel<<<NROWS, 256>>>(lg, target, out);
}